// round 14
// baseline (speedup 1.0000x reference)
#include <cuda_runtime.h>

#define NB 128
#define NT 96
#define ND 256
#define NH 256
#define NCM 512
#define GRID 128
#define NTHR 512
#define NGRP 8

typedef unsigned long long u64;

// rnn smem (floats): one act tile [16b][C_BSTR]; rows k<512 = s', 512..768 = h
#define C_BSTR  776
#define C_PART  12416                    // 8*64*17 = 8704
#define A_PART  21120                    // 512*5 = 2560
#define A_SCORE 23680                    // 512
#define SMEM_FLOATS 24192
#define SMEM_BYTES  (SMEM_FLOATS * 4)    // 96768 B

__device__ float g_Zb [NB*NT*ND];        // [b][t][d]
__device__ float g_ZPb[NB*NT*ND];
__device__ float g_LPb[NB*NT*ND];
__device__ float g_hall[(NT+1)*NB*NH];   // [t][b][h]
__device__ float g_sw  [NB*NCM];         // [b][cm]
__device__ float g_mm  [NCM*ND];
__device__ float g_memT[ND*NCM];
__device__ float g_W4r [4*NH*1280];      // row-major folded gate weights (dc0)
__device__ float g_W4p [4*NH*768];       // dc1 partials, orig cols [512:1280)
__device__ float g_W4q [4*192*NH*4 + 4096];   // in-loop blocked [g][k4'][hh][4]
__device__ float g_b4a [4*NH];
__device__ float g_b4b [4*NH];
__device__ float g_b4  [4*NH];
__device__ float g_Wscr[NCM*512];
__device__ float g_Wscq[64*NCM*4 + 6144];     // in-loop blocked [k4][cm][4]
__device__ float g_csc [NCM];
__device__ float g_wBG[256*1024*2 + 4096];    // pc weights [kp][col] k-pair interleave
__device__ float g_wBA[128*512*2 + 4096];
__device__ float g_G0[(size_t)NB*NT*1024];    // [b][t][g*256+hh]
__device__ float g_A0[(size_t)NB*NT*512];     // [b][t][cm]
__device__ unsigned int g_garrive [NGRP*64];
__device__ unsigned int g_grelease[NGRP*64];

#define FMA4(ACC, WV, AV) ACC = fmaf((WV).x,(AV).x, fmaf((WV).y,(AV).y, fmaf((WV).z,(AV).z, fmaf((WV).w,(AV).w,(ACC)))))

__device__ __forceinline__ void ffma2(u64& acc, u64 a, u64 b) {
    asm("fma.rn.f32x2 %0, %1, %2, %0;" : "+l"(acc) : "l"(a), "l"(b));
}
__device__ __forceinline__ void unpack2(u64 v, float& lo, float& hi) {
    asm("mov.b64 {%0, %1}, %2;" : "=f"(lo), "=f"(hi) : "l"(v));
}
__device__ __forceinline__ float pairsum(u64 v) {
    float lo, hi; unpack2(v, lo, hi); return lo + hi;
}
__device__ __forceinline__ unsigned atom_add_acqrel(unsigned* p, unsigned v) {
    unsigned r;
    asm volatile("atom.acq_rel.gpu.add.u32 %0, [%1], %2;" : "=r"(r) : "l"(p), "r"(v) : "memory");
    return r;
}
__device__ __forceinline__ unsigned ld_acquire(unsigned* p) {
    unsigned r;
    asm volatile("ld.acquire.gpu.u32 %0, [%1];" : "=r"(r) : "l"(p) : "memory");
    return r;
}
__device__ __forceinline__ void st_release(unsigned* p, unsigned v) {
    asm volatile("st.release.gpu.u32 [%0], %1;" :: "l"(p), "r"(v) : "memory");
}

// ---------------- prep1 ----------------
__global__ void prep1(const float* __restrict__ x, const float* __restrict__ xmean,
                      const int* __restrict__ cl32,
                      const float* __restrict__ gz_w,  const float* __restrict__ gz_b,
                      const float* __restrict__ gzp_w, const float* __restrict__ gzp_b,
                      const float* __restrict__ memory, const float* __restrict__ local_w)
{
    int tid  = blockIdx.x * blockDim.x + threadIdx.x;
    int nthr = gridDim.x * blockDim.x;
    bool is64 = (cl32[1] == 0);   // cluster vals 1..8 -> int64 high word of elem0 is 0

    for (int i = tid; i < NB*NT*ND; i += nthr) {
        int d = i & (ND - 1);
        int t = (i / ND) % NT;
        int b = i / (ND * NT);
        long long o = (((long long)b * 6) * NT + t) * ND + d;
        float xt  = x[o];
        float xl  = x[o + 1ll*NT*ND];
        float mk  = x[o + 2ll*NT*ND];
        float dt  = x[o + 3ll*NT*ND];
        float xlb = x[o + 4ll*NT*ND];
        float dtb = x[o + 5ll*NT*ND];
        float mean = xmean[t*ND + d];
        float dz  = expf(-fmaxf(dt  * gz_w[d]  + gz_b[d],  0.f));
        float dzp = expf(-fmaxf(dtb * gzp_w[d] + gzp_b[d], 0.f));
        float z  = mk*xt + (1.f - mk)*(dz *xl  + (1.f - dz )*mean);
        float zp = mk*xt + (1.f - mk)*(dzp*xlb + (1.f - dzp)*mean);
        g_Zb[i]  = z;
        g_ZPb[i] = zp;
        g_LPb[i] = local_w[d]*z + local_w[ND + d]*zp;
    }
    for (int i = tid; i < NCM*ND; i += nthr) {
        int d  = i & (ND - 1);
        int c  = i / (64 * ND);
        int cv = is64 ? cl32[2*d] : cl32[d];
        g_mm[i] = (cv == c + 1) ? memory[i] : 0.f;
    }
    for (int i = tid; i < ND*NCM; i += nthr) {
        int d = i / NCM, cm = i % NCM;
        g_memT[i] = memory[cm*ND + d];
    }
    for (int i = tid; i < NB*NH; i += nthr) g_hall[i] = 0.f;
    if (tid < NGRP*64) { g_garrive[tid] = 0u; g_grelease[tid] = 0u; }
}

// ---------------- prep2 ----------------
__global__ void prep2(const float* __restrict__ W_fc, const float* __restrict__ b_fc,
                      const float* __restrict__ local_w)
{
    __shared__ float A[16*256];
    int cmt = blockIdx.x;            // 0..31
    int tid = threadIdx.x;           // 512
    for (int idx = tid; idx < 16*256; idx += 512) {
        int ci = idx >> 8, d = idx & 255;
        float mmv = g_mm[(cmt*16 + ci)*ND + d];
        A[idx] = local_w[2*ND + d] * mmv;
        g_Wscr[(cmt*16 + ci)*512 + d] = mmv;
    }
    __syncthreads();
    int j = tid & 255, half = tid >> 8;
    float acc[8];
    #pragma unroll
    for (int i = 0; i < 8; ++i) acc[i] = 0.f;
    for (int d = 0; d < 256; ++d) {
        float wf = W_fc[d*ND + j];
        #pragma unroll
        for (int i = 0; i < 8; ++i) acc[i] = fmaf(A[(half*8+i)*256 + d], wf, acc[i]);
    }
    #pragma unroll
    for (int i = 0; i < 8; ++i)
        g_Wscr[(cmt*16 + half*8 + i)*512 + 256 + j] = acc[i];
    if (tid < 16) {
        float s = 0.f;
        for (int d = 0; d < 256; ++d) s += A[tid*256 + d] * b_fc[d];
        g_csc[cmt*16 + tid] = s;
    }
}

// ---------------- prep3 ----------------
__global__ void prep3(const float* __restrict__ W_i, const float* __restrict__ W_f,
                      const float* __restrict__ W_o, const float* __restrict__ W_c,
                      const float* __restrict__ b_i, const float* __restrict__ b_f,
                      const float* __restrict__ b_o, const float* __restrict__ b_c,
                      const float* __restrict__ W_fc, const float* __restrict__ b_fc)
{
    __shared__ float A1[16*128];
    __shared__ float A2[16*128];
    int bx = blockIdx.x;                 // 128
    int g = bx >> 5, hht = (bx >> 1) & 15, dc = bx & 1;
    int d0 = dc * 128;
    const float* Wg = (g == 0) ? W_i : (g == 1) ? W_f : (g == 2) ? W_o : W_c;
    const float* bg = (g == 0) ? b_i : (g == 1) ? b_f : (g == 2) ? b_o : b_c;
    int tid = threadIdx.x;   // 512

    for (int idx = tid; idx < 16*128; idx += 512) {
        int hi = idx >> 7, d = idx & 127;
        int row = hht*16 + hi;
        A1[idx] = Wg[row*1280 + 768 + d0 + d];
        A2[idx] = Wg[row*1280 + 512 + d0 + d];
    }
    if (dc == 0) {
        for (int idx = tid; idx < 16*512; idx += 512) {
            int hi = idx >> 9, k = idx & 511;
            int row = hht*16 + hi;
            g_W4r[(g*NH + row)*1280 + k] = Wg[row*1280 + k];
        }
    }
    __syncthreads();
    {
        int j = tid & 255, half = tid >> 8;
        float acc[8];
        #pragma unroll
        for (int i = 0; i < 8; ++i) acc[i] = 0.f;
        for (int d = 0; d < 128; ++d) {
            float wf = W_fc[(d0 + d)*ND + j];
            #pragma unroll
            for (int i = 0; i < 8; ++i) acc[i] = fmaf(A2[(half*8+i)*128 + d], wf, acc[i]);
        }
        #pragma unroll
        for (int i = 0; i < 8; ++i) {
            int hhr = hht*16 + half*8 + i;
            if (dc == 0) g_W4r[(g*NH + hhr)*1280 + 1024 + j] = Wg[hhr*1280 + 1024 + j] + acc[i];
            else         g_W4p[(g*NH + hhr)*768 + 512 + j] = acc[i];
        }
    }
    {
        int cm = tid;
        float acc[16];
        #pragma unroll
        for (int i = 0; i < 16; ++i) acc[i] = 0.f;
        for (int d = 0; d < 128; ++d) {
            float mt = g_memT[(d0 + d)*NCM + cm];
            #pragma unroll
            for (int i = 0; i < 16; ++i) acc[i] = fmaf(A1[i*128 + d], mt, acc[i]);
        }
        #pragma unroll
        for (int i = 0; i < 16; ++i) {
            if (dc == 0) g_W4r[(g*NH + hht*16 + i)*1280 + 512 + cm] = acc[i];
            else         g_W4p[(g*NH + hht*16 + i)*768 + cm] = acc[i];
        }
    }
    if (tid < 16) {
        float s = 0.f;
        for (int d = 0; d < 128; ++d) s += A2[tid*128 + d] * b_fc[d0 + d];
        if (dc == 0) g_b4a[g*NH + hht*16 + tid] = bg[hht*16 + tid] + s;
        else         g_b4b[g*NH + hht*16 + tid] = s;
    }
}

// ---------------- prep4: in-loop blocked weights + b4 + pc k-pair weights ----------------
#define PRN0 (4*192*256)
#define PRN1 (64*512)
#define PRN2 (4*NH)
#define PRN3 (256*1024)
#define PRN4 (128*512)
__global__ void prep4()
{
    int idx = blockIdx.x * blockDim.x + threadIdx.x;
    if (idx < PRN0) {
        int hh = idx & 255;
        int gk = idx >> 8;
        int g = gk / 192, k4 = gk % 192;
        float4 v = *(const float4*)&g_W4r[(g*NH + hh)*1280 + 512 + k4*4];
        float4 p = *(const float4*)&g_W4p[(g*NH + hh)*768 + k4*4];
        v.x += p.x; v.y += p.y; v.z += p.z; v.w += p.w;
        *(float4*)&g_W4q[idx*4] = v;
        return;
    }
    int j = idx - PRN0;
    if (j < PRN1) {
        int cm = j & 511, k4 = j >> 9;
        *(float4*)&g_Wscq[j*4] = *(const float4*)&g_Wscr[cm*512 + 256 + k4*4];
        return;
    }
    int m = j - PRN1;
    if (m < PRN2) { g_b4[m] = g_b4a[m] + g_b4b[m]; return; }
    int e = m - PRN2;
    if (e < PRN3) {           // wBG[kp][col] <- W4r[col][2kp..2kp+1]  (k<512 complete)
        int kp = e >> 10, col = e & 1023;
        *(float2*)&g_wBG[2*e] = make_float2(g_W4r[col*1280 + 2*kp], g_W4r[col*1280 + 2*kp + 1]);
        return;
    }
    int q = e - PRN3;
    if (q < PRN4) {           // wBA[kp][cm] <- Wscr[cm][2kp..2kp+1]
        int kp = q >> 9, cm = q & 511;
        *(float2*)&g_wBA[2*q] = make_float2(g_Wscr[cm*512 + 2*kp], g_Wscr[cm*512 + 2*kp + 1]);
    }
}

// ---------------- pc_gemm v2: k-pair f32x2, 4r x 8c per thread ----------------
#define PCBODY(W, K2) { \
    u64 a0_ = *(const u64*)&sa[(r0+0)*68 + (K2)]; \
    u64 a1_ = *(const u64*)&sa[(r0+1)*68 + (K2)]; \
    u64 a2_ = *(const u64*)&sa[(r0+2)*68 + (K2)]; \
    u64 a3_ = *(const u64*)&sa[(r0+3)*68 + (K2)]; \
    _Pragma("unroll") \
    for (int q_ = 0; q_ < 4; ++q_) { \
        u64 wx_ = __double_as_longlong((W)[q_].x); \
        u64 wy_ = __double_as_longlong((W)[q_].y); \
        ffma2(acc[0][2*q_], wx_, a0_); ffma2(acc[0][2*q_+1], wy_, a0_); \
        ffma2(acc[1][2*q_], wx_, a1_); ffma2(acc[1][2*q_+1], wy_, a1_); \
        ffma2(acc[2][2*q_], wx_, a2_); ffma2(acc[2][2*q_+1], wy_, a2_); \
        ffma2(acc[3][2*q_], wx_, a3_); ffma2(acc[3][2*q_+1], wy_, a3_); } }

__global__ void __launch_bounds__(256, 2) pc_gemm()
{
    __shared__ float sa[64*68];
    int rt = blockIdx.x, ct = blockIdx.y;          // (192, 12)
    bool isG = (ct < 8);
    const int COLS = isG ? 1024 : 512;
    const int KK   = isG ? 512 : 256;
    const float* WB   = isG ? g_wBG : g_wBA;
    const float* BIAS = isG ? g_b4 : g_csc;
    float* OUT = isG ? g_G0 : g_A0;
    int c0g = (isG ? ct : ct - 8) * 128;
    int tid = threadIdx.x;
    int tc = tid & 15, tr = tid >> 4;
    int r0 = tr * 4;
    int cc = c0g + tc * 8;
    int R0 = rt * 64;
    u64 acc[4][8];
    #pragma unroll
    for (int i = 0; i < 4; ++i)
        #pragma unroll
        for (int jj = 0; jj < 8; ++jj) acc[i][jj] = 0ull;

    const double2* wd = (const double2*)WB + (cc >> 1);
    const int wstep = COLS >> 1;       // double2 per kp
    double2 WA0[4], WA1[4];
    #pragma unroll
    for (int q = 0; q < 4; ++q) { WA0[q] = wd[q]; WA1[q] = wd[wstep + q]; }
    const double2* wnext = wd + 2*wstep;

    for (int kc = 0; kc < KK; kc += 64) {
        for (int i = tid; i < 1024; i += 256) {    // stage acts 64r x 64k
            int r = i >> 4, k4 = i & 15;
            int R = R0 + r;
            int kg = kc + k4*4;
            float4 v;
            if (isG) v = (kg < 256) ? *(const float4*)&g_Zb[(R << 8) + kg]
                                    : *(const float4*)&g_ZPb[(R << 8) + kg - 256];
            else     v = *(const float4*)&g_LPb[(R << 8) + kg];
            *(float4*)&sa[r*68 + k4*4] = v;
        }
        __syncthreads();
        #pragma unroll 4
        for (int kk = 0; kk < 32; kk += 2) {
            double2 N0[4], N1[4];
            #pragma unroll
            for (int q = 0; q < 4; ++q) N0[q] = wnext[q];
            PCBODY(WA0, kk*2)
            #pragma unroll
            for (int q = 0; q < 4; ++q) N1[q] = wnext[wstep + q];
            PCBODY(WA1, kk*2 + 2)
            #pragma unroll
            for (int q = 0; q < 4; ++q) { WA0[q] = N0[q]; WA1[q] = N1[q]; }
            wnext += 2*wstep;
        }
        __syncthreads();
    }
    #pragma unroll
    for (int i = 0; i < 4; ++i) {
        int R = R0 + r0 + i;
        float o[8];
        #pragma unroll
        for (int jj = 0; jj < 8; ++jj) o[jj] = pairsum(acc[i][jj]) + BIAS[cc + jj];
        *(float4*)&OUT[(size_t)R*COLS + cc]     = make_float4(o[0], o[1], o[2], o[3]);
        *(float4*)&OUT[(size_t)R*COLS + cc + 4] = make_float4(o[4], o[5], o[6], o[7]);
    }
}

// ---------------- per-group barrier ----------------
__device__ __forceinline__ void group_sync(int grp, unsigned int& gen)
{
    __syncthreads();
    if (threadIdx.x == 0) {
        unsigned int target = gen + 1u;
        unsigned int a = atom_add_acqrel(&g_garrive[grp*64], 1u) + 1u;
        if (a == target * 16u) {
            st_release(&g_grelease[grp*64], target);
        } else {
            while (ld_acquire(&g_grelease[grp*64]) < target) { }
        }
    }
    gen += 1u;
    __syncthreads();
}

// ---------------- persistent recurrence ----------------
__global__ void __launch_bounds__(NTHR, 1)
rnn_kernel(const float* __restrict__ global_w)
{
    extern __shared__ float sm[];
    const int cta = blockIdx.x, tid = threadIdx.x;
    const int lane = tid & 31, wid = tid >> 5;
    const int grp = cta >> 4, local = cta & 15;
    const int bhalf = local >> 3, ccl = local & 7;
    const int a_b0 = grp*16 + bhalf*8;
    const int a_ml = tid & 63, a_bh = (tid >> 6) & 1, a_ks = tid >> 7;
    const int sub = local;
    const int c_b0 = grp*16;
    const int c_hl = tid & 15, c_ks = tid >> 6;
    const int hh = sub*16 + c_hl;
    unsigned int gen = 0;

    float gwreg = global_w[ccl];
    float creg = 0.f;

    // pre-stage h(0)=0 into act rows 512..768 for all 16 group batches
    for (int idx = tid; idx < 16*64; idx += NTHR) {
        int bi = idx >> 6, k4 = idx & 63;
        *(float4*)&sm[bi*C_BSTR + 512 + k4*4] =
            *(const float4*)&g_hall[((c_b0 + bi) << 8) + k4*4];
    }
    __syncthreads();

    for (int t = 0; t < NT; ++t) {
        // prefetch precomputed step-t contributions
        float g0r0 = 0.f, g0r1 = 0.f, g0r2 = 0.f, g0r3 = 0.f;
        if (tid < 256) {
            int bi = tid >> 4, h2 = sub*16 + (tid & 15);
            const float* p = g_G0 + (size_t)((c_b0 + bi)*NT + t)*1024 + h2;
            g0r0 = __ldcg(p);       g0r1 = __ldcg(p + 256);
            g0r2 = __ldcg(p + 512); g0r3 = __ldcg(p + 768);
        }
        float a0r = __ldcg(&g_A0[(size_t)((a_b0 + (tid >> 6))*NT + t)*512 + ccl*64 + (tid & 63)]);

        // ===== Phase A: scores(h) + A0 + softmax -> s'(t) in g_sw =====
        {
            u64 acc2[4] = {0ull, 0ull, 0ull, 0ull};
            {
                const double2* wp = (const double2*)g_Wscq + (a_ks*16)*NCM + (ccl*64 + a_ml);
                const float*  ak = sm + (bhalf*8 + a_bh*4)*C_BSTR + 512 + a_ks*64;
                #define AHALF(IT, WV) { \
                    u64 w01_ = __double_as_longlong((WV).x); \
                    u64 w23_ = __double_as_longlong((WV).y); \
                    const float* app_ = ak + (IT)*4; \
                    _Pragma("unroll") \
                    for (int j_ = 0; j_ < 4; ++j_) { \
                        u64 a01_ = *(const u64*)(app_ + j_*C_BSTR); \
                        u64 a23_ = *(const u64*)(app_ + j_*C_BSTR + 2); \
                        ffma2(acc2[j_], w01_, a01_); \
                        ffma2(acc2[j_], w23_, a23_); } }
                double2 V0 = wp[0], V1 = wp[NCM];
                #pragma unroll 1
                for (int it = 0; it < 16; it += 2) {
                    double2 N0 = wp[(it+2)*NCM];
                    AHALF(it, V0)
                    double2 N1 = wp[(it+3)*NCM];
                    AHALF(it+1, V1)
                    V0 = N0; V1 = N1;
                }
                #undef AHALF
            }
            {
                int base = A_PART + ((a_ks*64 + a_ml)*2 + a_bh)*5;
                #pragma unroll
                for (int jj = 0; jj < 4; ++jj) sm[base + jj] = pairsum(acc2[jj]);
            }
            __syncthreads();
            {
                int bl = tid >> 6, m = tid & 63;
                float s = a0r;
                #pragma unroll
                for (int ks = 0; ks < 4; ++ks)
                    s += sm[A_PART + ((ks*64 + m)*2 + (bl >> 2))*5 + (bl & 3)];
                sm[A_SCORE + bl*64 + m] = s;
            }
            __syncthreads();
            if (wid < 8) {
                float v0 = sm[A_SCORE + wid*64 + lane];
                float v1 = sm[A_SCORE + wid*64 + 32 + lane];
                float mx = fmaxf(v0, v1);
                #pragma unroll
                for (int o = 16; o; o >>= 1) mx = fmaxf(mx, __shfl_xor_sync(0xffffffffu, mx, o));
                float e0 = expf(v0 - mx), e1 = expf(v1 - mx);
                float s = e0 + e1;
                #pragma unroll
                for (int o = 16; o; o >>= 1) s += __shfl_xor_sync(0xffffffffu, s, o);
                float sc = gwreg / s;
                int b = a_b0 + wid;
                __stcg(&g_sw[b*NCM + ccl*64 + lane],      e0*sc);
                __stcg(&g_sw[b*NCM + ccl*64 + 32 + lane], e1*sc);
            }
        }
        group_sync(grp, gen);   // s'(t) complete group-wide

        // stage s'(t) into act rows [0:512)
        for (int idx = tid; idx < 16*128; idx += NTHR) {
            int bi = idx >> 7, k4 = idx & 127;
            int b = c_b0 + bi, k = k4*4;
            *(float4*)&sm[bi*C_BSTR + k] = __ldcg((const float4*)&g_sw[(b << 9) + k]);
        }
        __syncthreads();

        // ===== Phase C: 4-gate GEMM over K=768 [s',h], k-pair f32x2 =====
        {
            u64 acc2[16];
            #pragma unroll
            for (int i = 0; i < 16; ++i) acc2[i] = 0ull;
            {
                const int c_bq = (tid >> 4) & 3;
                const int k24 = c_ks * 24;
                const double2* w0 = (const double2*)g_W4q + ((0*192 + k24)*NH + hh);
                const double2* w1 = (const double2*)g_W4q + ((1*192 + k24)*NH + hh);
                const double2* w2 = (const double2*)g_W4q + ((2*192 + k24)*NH + hh);
                const double2* w3 = (const double2*)g_W4q + ((3*192 + k24)*NH + hh);
                const float*  ak = sm + (c_bq*4)*C_BSTR + c_ks*96;
                #define CHALF(IT, WA, WB2, WC, WD) { \
                    u64 wa01_ = __double_as_longlong((WA).x),  wa23_ = __double_as_longlong((WA).y); \
                    u64 wb01_ = __double_as_longlong((WB2).x), wb23_ = __double_as_longlong((WB2).y); \
                    u64 wc01_ = __double_as_longlong((WC).x),  wc23_ = __double_as_longlong((WC).y); \
                    u64 wd01_ = __double_as_longlong((WD).x),  wd23_ = __double_as_longlong((WD).y); \
                    const float* app_ = ak + (IT)*4; \
                    _Pragma("unroll") \
                    for (int j_ = 0; j_ < 4; ++j_) { \
                        u64 a01_ = *(const u64*)(app_ + j_*C_BSTR); \
                        u64 a23_ = *(const u64*)(app_ + j_*C_BSTR + 2); \
                        ffma2(acc2[0*4+j_], wa01_, a01_); ffma2(acc2[0*4+j_], wa23_, a23_); \
                        ffma2(acc2[1*4+j_], wb01_, a01_); ffma2(acc2[1*4+j_], wb23_, a23_); \
                        ffma2(acc2[2*4+j_], wc01_, a01_); ffma2(acc2[2*4+j_], wc23_, a23_); \
                        ffma2(acc2[3*4+j_], wd01_, a01_); ffma2(acc2[3*4+j_], wd23_, a23_); } }
                double2 Wa0 = w0[0],  Wb0 = w1[0],  Wc0 = w2[0],  Wd0 = w3[0];
                double2 Wa1 = w0[NH], Wb1 = w1[NH], Wc1 = w2[NH], Wd1 = w3[NH];
                #pragma unroll 1
                for (int it = 0; it < 24; it += 2) {
                    double2 Na = w0[(it+2)*NH], Nb = w1[(it+2)*NH],
                            Nc = w2[(it+2)*NH], Nd = w3[(it+2)*NH];
                    CHALF(it, Wa0, Wb0, Wc0, Wd0)
                    double2 Ma = w0[(it+3)*NH], Mb = w1[(it+3)*NH],
                            Mc = w2[(it+3)*NH], Md = w3[(it+3)*NH];
                    CHALF(it+1, Wa1, Wb1, Wc1, Wd1)
                    Wa0 = Na; Wb0 = Nb; Wc0 = Nc; Wd0 = Nd;
                    Wa1 = Ma; Wb1 = Mb; Wc1 = Mc; Wd1 = Md;
                }
                #undef CHALF
            }
            {   // partials to disjoint region (no pre-sync needed)
                const int c_bq = (tid >> 4) & 3;
                int base = C_PART + (c_ks*64 + c_bq*16 + c_hl)*17;
                #pragma unroll
                for (int v = 0; v < 16; ++v) sm[base + v] = pairsum(acc2[v]);
            }
            __syncthreads();
            if (tid < 256) {   // reduce 8 ks + G0, gates, register state
                int hl2 = tid & 15, bi = tid >> 4;
                int bq = bi >> 2, jx = bi & 3;
                int b = c_b0 + bi, h2 = sub*16 + hl2;
                float g0 = g0r0, g1 = g0r1, g2 = g0r2, g3 = g0r3;
                #pragma unroll
                for (int ks = 0; ks < 8; ++ks) {
                    const float* p = &sm[C_PART + (ks*64 + bq*16 + hl2)*17 + jx];
                    g0 += p[0]; g1 += p[4]; g2 += p[8]; g3 += p[12];
                }
                float ig = 1.f / (1.f + expf(-g0));
                float fg = 1.f / (1.f + expf(-g1));
                float og = 1.f / (1.f + expf(-g2));
                float cg = tanhf(g3);
                creg = fg * creg + ig * cg;
                float hn = og * tanhf(creg);
                __stcg(&g_hall[(((t+1)*NB + b) << 8) + h2], hn);
            }
        }
        group_sync(grp, gen);   // h(t+1) complete group-wide

        if (t + 1 < NT) {   // stage h(t+1) into act rows 512..768 (all 16 batches)
            for (int idx = tid; idx < 16*64; idx += NTHR) {
                int bi = idx >> 6, k4 = idx & 63;
                *(float4*)&sm[bi*C_BSTR + 512 + k4*4] =
                    __ldcg((const float4*)&g_hall[(((t+1)*NB + c_b0 + bi) << 8) + k4*4]);
            }
            __syncthreads();
        }
    }
}

// ---------------- final: out[b,t,:] = h_{t+1} @ W_fc^T + b_fc ----------------
__global__ void out_gemm(const float* __restrict__ W_fc, const float* __restrict__ b_fc,
                         float* __restrict__ out)
{
    __shared__ float sa[16*256];
    int rt = blockIdx.x >> 2, dt = blockIdx.x & 3;
    int tid = threadIdx.x;           // 256
    int r0 = rt * 16;
    for (int idx = tid; idx < 16*64; idx += 256) {
        int row = idx >> 6, k4 = idx & 63;
        int r = r0 + row, b = r / NT, t = r % NT;
        *(float4*)&sa[row*256 + k4*4] =
            *(const float4*)&g_hall[(((t+1)*NB + b) << 8) + k4*4];
    }
    __syncthreads();
    int dl = tid & 63, rl = tid >> 6;
    int d = dt*64 + dl;
    float acc[4];
    #pragma unroll
    for (int i = 0; i < 4; ++i) acc[i] = 0.f;
    const float* wrow = W_fc + d*NH;
    #pragma unroll 4
    for (int k4 = 0; k4 < 64; ++k4) {
        float4 wv = *(const float4*)(wrow + k4*4);
        #pragma unroll
        for (int i = 0; i < 4; ++i) {
            float4 av = *(const float4*)&sa[(rl*4 + i)*256 + k4*4];
            FMA4(acc[i], wv, av);
        }
    }
    float bb = b_fc[d];
    #pragma unroll
    for (int i = 0; i < 4; ++i)
        out[(r0 + rl*4 + i)*ND + d] = acc[i] + bb;
}

// ---------------- launch ----------------
extern "C" void kernel_launch(void* const* d_in, const int* in_sizes, int n_in,
                              void* d_out, int out_size)
{
    const float* x        = (const float*)d_in[0];
    const float* xmean    = (const float*)d_in[1];
    const int*   clus     = (const int*)  d_in[2];
    const float* W_i      = (const float*)d_in[3];
    const float* b_i      = (const float*)d_in[4];
    const float* W_f      = (const float*)d_in[5];
    const float* b_f      = (const float*)d_in[6];
    const float* W_o      = (const float*)d_in[7];
    const float* b_o      = (const float*)d_in[8];
    const float* W_c      = (const float*)d_in[9];
    const float* b_c      = (const float*)d_in[10];
    const float* W_fc     = (const float*)d_in[11];
    const float* b_fc     = (const float*)d_in[12];
    const float* gz_w     = (const float*)d_in[13];
    const float* gz_b     = (const float*)d_in[14];
    const float* gzp_w    = (const float*)d_in[15];
    const float* gzp_b    = (const float*)d_in[16];
    const float* memory   = (const float*)d_in[17];
    const float* local_w  = (const float*)d_in[18];
    const float* global_w = (const float*)d_in[19];
    float* out = (float*)d_out;

    cudaFuncSetAttribute(rnn_kernel, cudaFuncAttributeMaxDynamicSharedMemorySize, SMEM_BYTES);

    prep1<<<512, 256>>>(x, xmean, clus, gz_w, gz_b, gzp_w, gzp_b, memory, local_w);
    prep2<<<32, 512>>>(W_fc, b_fc, local_w);
    prep3<<<128, 512>>>(W_i, W_f, W_o, W_c, b_i, b_f, b_o, b_c, W_fc, b_fc);
    prep4<<<2180, 256>>>();
    pc_gemm<<<dim3(192, 12), 256>>>();
    rnn_kernel<<<GRID, NTHR, SMEM_BYTES>>>(global_w);
    out_gemm<<<3072, 256>>>(W_fc, b_fc, out);
}

// round 15
// speedup vs baseline: 1.9504x; 1.9504x over previous
#include <cuda_runtime.h>

#define NB 128
#define NT 96
#define ND 256
#define NH 256
#define NCM 512
#define GRID 128
#define NTHR 512
#define NGRP 8

typedef unsigned long long u64;

// rnn smem (floats): one act tile [16b][C_BSTR]; rows k<512 = s', 512..768 = h
#define C_BSTR  776
#define C_PART  12416                    // partials: 8*64*17 = 8704
#define A_PART  21120                    // 512*5 = 2560
#define A_SCORE 23680                    // 512
#define SMEM_FLOATS 24192
#define SMEM_BYTES  (SMEM_FLOATS * 4)    // 96768 B

__device__ float g_Zb [NB*NT*ND];        // [b][t][d]
__device__ float g_ZPb[NB*NT*ND];
__device__ float g_LPb[NB*NT*ND];
__device__ float g_hall[(NT+1)*NB*NH];   // [t][b][h]
__device__ float g_sw  [NB*NCM];         // [b][cm]
__device__ float g_mm  [NCM*ND];
__device__ float g_memT[ND*NCM];
__device__ float g_W4r [4*NH*1280];      // row-major folded gate weights (dc0)
__device__ float g_W4p [4*NH*768];       // dc1 partials, orig cols [512:1280)
__device__ float g_W4q [4*192*NH*4 + 4096];   // in-loop blocked [g][k4'][hh][4]
__device__ float g_b4a [4*NH];
__device__ float g_b4b [4*NH];
__device__ float g_b4  [4*NH];
__device__ float g_Wscr[NCM*512];
__device__ float g_Wscq[64*NCM*4 + 6144];     // in-loop blocked [k4][cm][4]
__device__ float g_csc [NCM];
__device__ float g_G0[(size_t)NB*NT*1024];    // [b][t][g*256+hh]
__device__ float g_A0[(size_t)NB*NT*512];     // [b][t][cm]
__device__ unsigned int g_garrive [NGRP*64];
__device__ unsigned int g_grelease[NGRP*64];

#define FMA4(ACC, WV, AV) ACC = fmaf((WV).x,(AV).x, fmaf((WV).y,(AV).y, fmaf((WV).z,(AV).z, fmaf((WV).w,(AV).w,(ACC)))))

__device__ __forceinline__ void ffma2(u64& acc, u64 a, u64 b) {
    asm("fma.rn.f32x2 %0, %1, %2, %0;" : "+l"(acc) : "l"(a), "l"(b));
}
__device__ __forceinline__ u64 dup2(float v) {
    u64 r; asm("mov.b64 %0, {%1, %1};" : "=l"(r) : "f"(v)); return r;
}
__device__ __forceinline__ void unpack2(u64 v, float& lo, float& hi) {
    asm("mov.b64 {%0, %1}, %2;" : "=f"(lo), "=f"(hi) : "l"(v));
}
__device__ __forceinline__ float pairsum(u64 v) {
    float lo, hi; unpack2(v, lo, hi); return lo + hi;
}
__device__ __forceinline__ unsigned atom_add_acqrel(unsigned* p, unsigned v) {
    unsigned r;
    asm volatile("atom.acq_rel.gpu.add.u32 %0, [%1], %2;" : "=r"(r) : "l"(p), "r"(v) : "memory");
    return r;
}
__device__ __forceinline__ unsigned ld_acquire(unsigned* p) {
    unsigned r;
    asm volatile("ld.acquire.gpu.u32 %0, [%1];" : "=r"(r) : "l"(p) : "memory");
    return r;
}
__device__ __forceinline__ void st_release(unsigned* p, unsigned v) {
    asm volatile("st.release.gpu.u32 [%0], %1;" :: "l"(p), "r"(v) : "memory");
}

// ---------------- prep1 ----------------
__global__ void prep1(const float* __restrict__ x, const float* __restrict__ xmean,
                      const int* __restrict__ cl32,
                      const float* __restrict__ gz_w,  const float* __restrict__ gz_b,
                      const float* __restrict__ gzp_w, const float* __restrict__ gzp_b,
                      const float* __restrict__ memory, const float* __restrict__ local_w)
{
    int tid  = blockIdx.x * blockDim.x + threadIdx.x;
    int nthr = gridDim.x * blockDim.x;
    bool is64 = (cl32[1] == 0);   // cluster vals 1..8 -> int64 high word of elem0 is 0

    for (int i = tid; i < NB*NT*ND; i += nthr) {
        int d = i & (ND - 1);
        int t = (i / ND) % NT;
        int b = i / (ND * NT);
        long long o = (((long long)b * 6) * NT + t) * ND + d;
        float xt  = x[o];
        float xl  = x[o + 1ll*NT*ND];
        float mk  = x[o + 2ll*NT*ND];
        float dt  = x[o + 3ll*NT*ND];
        float xlb = x[o + 4ll*NT*ND];
        float dtb = x[o + 5ll*NT*ND];
        float mean = xmean[t*ND + d];
        float dz  = expf(-fmaxf(dt  * gz_w[d]  + gz_b[d],  0.f));
        float dzp = expf(-fmaxf(dtb * gzp_w[d] + gzp_b[d], 0.f));
        float z  = mk*xt + (1.f - mk)*(dz *xl  + (1.f - dz )*mean);
        float zp = mk*xt + (1.f - mk)*(dzp*xlb + (1.f - dzp)*mean);
        g_Zb[i]  = z;
        g_ZPb[i] = zp;
        g_LPb[i] = local_w[d]*z + local_w[ND + d]*zp;
    }
    for (int i = tid; i < NCM*ND; i += nthr) {
        int d  = i & (ND - 1);
        int c  = i / (64 * ND);
        int cv = is64 ? cl32[2*d] : cl32[d];
        g_mm[i] = (cv == c + 1) ? memory[i] : 0.f;
    }
    for (int i = tid; i < ND*NCM; i += nthr) {
        int d = i / NCM, cm = i % NCM;
        g_memT[i] = memory[cm*ND + d];
    }
    for (int i = tid; i < NB*NH; i += nthr) g_hall[i] = 0.f;
    if (tid < NGRP*64) { g_garrive[tid] = 0u; g_grelease[tid] = 0u; }
}

// ---------------- prep2 ----------------
__global__ void prep2(const float* __restrict__ W_fc, const float* __restrict__ b_fc,
                      const float* __restrict__ local_w)
{
    __shared__ float A[16*256];
    int cmt = blockIdx.x;            // 0..31
    int tid = threadIdx.x;           // 512
    for (int idx = tid; idx < 16*256; idx += 512) {
        int ci = idx >> 8, d = idx & 255;
        float mmv = g_mm[(cmt*16 + ci)*ND + d];
        A[idx] = local_w[2*ND + d] * mmv;
        g_Wscr[(cmt*16 + ci)*512 + d] = mmv;
    }
    __syncthreads();
    int j = tid & 255, half = tid >> 8;
    float acc[8];
    #pragma unroll
    for (int i = 0; i < 8; ++i) acc[i] = 0.f;
    for (int d = 0; d < 256; ++d) {
        float wf = W_fc[d*ND + j];
        #pragma unroll
        for (int i = 0; i < 8; ++i) acc[i] = fmaf(A[(half*8+i)*256 + d], wf, acc[i]);
    }
    #pragma unroll
    for (int i = 0; i < 8; ++i)
        g_Wscr[(cmt*16 + half*8 + i)*512 + 256 + j] = acc[i];
    if (tid < 16) {
        float s = 0.f;
        for (int d = 0; d < 256; ++d) s += A[tid*256 + d] * b_fc[d];
        g_csc[cmt*16 + tid] = s;
    }
}

// ---------------- prep3 ----------------
__global__ void prep3(const float* __restrict__ W_i, const float* __restrict__ W_f,
                      const float* __restrict__ W_o, const float* __restrict__ W_c,
                      const float* __restrict__ b_i, const float* __restrict__ b_f,
                      const float* __restrict__ b_o, const float* __restrict__ b_c,
                      const float* __restrict__ W_fc, const float* __restrict__ b_fc)
{
    __shared__ float A1[16*128];
    __shared__ float A2[16*128];
    int bx = blockIdx.x;                 // 128
    int g = bx >> 5, hht = (bx >> 1) & 15, dc = bx & 1;
    int d0 = dc * 128;
    const float* Wg = (g == 0) ? W_i : (g == 1) ? W_f : (g == 2) ? W_o : W_c;
    const float* bg = (g == 0) ? b_i : (g == 1) ? b_f : (g == 2) ? b_o : b_c;
    int tid = threadIdx.x;   // 512

    for (int idx = tid; idx < 16*128; idx += 512) {
        int hi = idx >> 7, d = idx & 127;
        int row = hht*16 + hi;
        A1[idx] = Wg[row*1280 + 768 + d0 + d];
        A2[idx] = Wg[row*1280 + 512 + d0 + d];
    }
    if (dc == 0) {
        for (int idx = tid; idx < 16*512; idx += 512) {
            int hi = idx >> 9, k = idx & 511;
            int row = hht*16 + hi;
            g_W4r[(g*NH + row)*1280 + k] = Wg[row*1280 + k];
        }
    }
    __syncthreads();
    {
        int j = tid & 255, half = tid >> 8;
        float acc[8];
        #pragma unroll
        for (int i = 0; i < 8; ++i) acc[i] = 0.f;
        for (int d = 0; d < 128; ++d) {
            float wf = W_fc[(d0 + d)*ND + j];
            #pragma unroll
            for (int i = 0; i < 8; ++i) acc[i] = fmaf(A2[(half*8+i)*128 + d], wf, acc[i]);
        }
        #pragma unroll
        for (int i = 0; i < 8; ++i) {
            int hhr = hht*16 + half*8 + i;
            if (dc == 0) g_W4r[(g*NH + hhr)*1280 + 1024 + j] = Wg[hhr*1280 + 1024 + j] + acc[i];
            else         g_W4p[(g*NH + hhr)*768 + 512 + j] = acc[i];
        }
    }
    {
        int cm = tid;
        float acc[16];
        #pragma unroll
        for (int i = 0; i < 16; ++i) acc[i] = 0.f;
        for (int d = 0; d < 128; ++d) {
            float mt = g_memT[(d0 + d)*NCM + cm];
            #pragma unroll
            for (int i = 0; i < 16; ++i) acc[i] = fmaf(A1[i*128 + d], mt, acc[i]);
        }
        #pragma unroll
        for (int i = 0; i < 16; ++i) {
            if (dc == 0) g_W4r[(g*NH + hht*16 + i)*1280 + 512 + cm] = acc[i];
            else         g_W4p[(g*NH + hht*16 + i)*768 + cm] = acc[i];
        }
    }
    if (tid < 16) {
        float s = 0.f;
        for (int d = 0; d < 128; ++d) s += A2[tid*128 + d] * b_fc[d0 + d];
        if (dc == 0) g_b4a[g*NH + hht*16 + tid] = bg[hht*16 + tid] + s;
        else         g_b4b[g*NH + hht*16 + tid] = s;
    }
}

// ---------------- prep4: in-loop blocked layouts + b4 ----------------
__global__ void prep4()
{
    int idx = blockIdx.x * blockDim.x + threadIdx.x;
    if (idx < 4*192*256) {
        int hh = idx & 255;
        int gk = idx >> 8;
        int g = gk / 192, k4 = gk % 192;
        float4 v = *(const float4*)&g_W4r[(g*NH + hh)*1280 + 512 + k4*4];
        float4 p = *(const float4*)&g_W4p[(g*NH + hh)*768 + k4*4];
        v.x += p.x; v.y += p.y; v.z += p.z; v.w += p.w;
        *(float4*)&g_W4q[idx*4] = v;
        return;
    }
    int j = idx - 4*192*256;
    if (j < 64*512) {
        int cm = j & 511, k4 = j >> 9;
        *(float4*)&g_Wscq[j*4] = *(const float4*)&g_Wscr[cm*512 + 256 + k4*4];
        return;
    }
    int m = j - 64*512;
    if (m < 4*NH) g_b4[m] = g_b4a[m] + g_b4b[m];
}

// ---------------- pc_gemm (R12 proven version): G0, A0 ----------------
__global__ void __launch_bounds__(256, 4) pc_gemm()
{
    __shared__ float sa[64*68];
    __shared__ float sw[64*68];
    int rt = blockIdx.x;             // 0..191, rows = b*96+t
    int yy = blockIdx.y;             // 0..23
    bool isG = (yy < 16);
    int ct = isG ? yy : (yy - 16);
    const int COLS = isG ? 1024 : 512;
    const int KK   = isG ? 512 : 256;
    const int KROW = isG ? 1280 : 512;
    const float* WR   = isG ? g_W4r : g_Wscr;
    const float* BIAS = isG ? g_b4 : g_csc;
    float* OUT = isG ? g_G0 : g_A0;
    int tid = threadIdx.x;
    int tr = tid >> 4, tc = tid & 15;
    int r0 = tr*4, c0l = tc*4;
    u64 acc[4][2];
    #pragma unroll
    for (int i = 0; i < 4; ++i) { acc[i][0] = 0ull; acc[i][1] = 0ull; }

    for (int kc = 0; kc < KK; kc += 64) {
        for (int i = tid; i < 1024; i += 256) {      // acts 64r x 64k (float4)
            int r = i >> 4, k4 = i & 15;
            int R = rt*64 + r;
            int kg = kc + k4*4;
            const float* src;
            if (isG) src = (kg < 256) ? &g_Zb[(R << 8) + kg] : &g_ZPb[(R << 8) + kg - 256];
            else     src = &g_LPb[(R << 8) + kg];
            *(float4*)&sa[r*68 + k4*4] = *(const float4*)src;
        }
        for (int e = tid; e < 4096; e += 256) {      // weights 64c x 64k -> sw[k][c]
            int c = e >> 6, k = e & 63;
            sw[k*68 + c] = WR[(size_t)(ct*64 + c)*KROW + kc + k];
        }
        __syncthreads();
        #pragma unroll 4
        for (int k = 0; k < 64; ++k) {
            double2 wv = *(const double2*)&sw[k*68 + c0l];
            u64 w01 = __double_as_longlong(wv.x);
            u64 w23 = __double_as_longlong(wv.y);
            #pragma unroll
            for (int i = 0; i < 4; ++i) {
                u64 av = dup2(sa[(r0 + i)*68 + k]);
                ffma2(acc[i][0], av, w01);
                ffma2(acc[i][1], av, w23);
            }
        }
        __syncthreads();
    }
    float4 bv = *(const float4*)&BIAS[ct*64 + c0l];
    #pragma unroll
    for (int i = 0; i < 4; ++i) {
        float o0, o1, o2, o3;
        unpack2(acc[i][0], o0, o1);
        unpack2(acc[i][1], o2, o3);
        int R = rt*64 + r0 + i;
        float4 ov = make_float4(o0 + bv.x, o1 + bv.y, o2 + bv.z, o3 + bv.w);
        *(float4*)&OUT[(size_t)R*COLS + ct*64 + c0l] = ov;
    }
}

// ---------------- per-group barrier ----------------
__device__ __forceinline__ void group_sync(int grp, unsigned int& gen)
{
    __syncthreads();
    if (threadIdx.x == 0) {
        unsigned int target = gen + 1u;
        unsigned int a = atom_add_acqrel(&g_garrive[grp*64], 1u) + 1u;
        if (a == target * 16u) {
            st_release(&g_grelease[grp*64], target);
        } else {
            while (ld_acquire(&g_grelease[grp*64]) < target) { }
        }
    }
    gen += 1u;
    __syncthreads();
}

// ---------------- persistent recurrence (unified act tile) ----------------
__global__ void __launch_bounds__(NTHR, 1)
rnn_kernel(const float* __restrict__ global_w)
{
    extern __shared__ float sm[];
    const int cta = blockIdx.x, tid = threadIdx.x;
    const int lane = tid & 31, wid = tid >> 5;
    const int grp = cta >> 4, local = cta & 15;
    const int bhalf = local >> 3, ccl = local & 7;
    const int a_b0 = grp*16 + bhalf*8;
    const int a_ml = tid & 63, a_bh = (tid >> 6) & 1, a_ks = tid >> 7;
    const int sub = local;
    const int c_b0 = grp*16;
    const int c_hl = tid & 15, c_ks = tid >> 6;
    const int hh = sub*16 + c_hl;
    unsigned int gen = 0;

    float gwreg = global_w[ccl];
    float creg = 0.f;

    // pre-stage h(0)=0 into act rows 512..768 for all 16 group batches
    for (int idx = tid; idx < 16*64; idx += NTHR) {
        int bi = idx >> 6, k4 = idx & 63;
        *(float4*)&sm[bi*C_BSTR + 512 + k4*4] =
            *(const float4*)&g_hall[((c_b0 + bi) << 8) + k4*4];
    }
    __syncthreads();

    for (int t = 0; t < NT; ++t) {
        // prefetch precomputed step-t contributions
        float g0r0 = 0.f, g0r1 = 0.f, g0r2 = 0.f, g0r3 = 0.f;
        if (tid < 256) {
            int bi = tid >> 4, h2 = sub*16 + (tid & 15);
            const float* p = g_G0 + (size_t)((c_b0 + bi)*NT + t)*1024 + h2;
            g0r0 = __ldcg(p);       g0r1 = __ldcg(p + 256);
            g0r2 = __ldcg(p + 512); g0r3 = __ldcg(p + 768);
        }
        float a0r = __ldcg(&g_A0[(size_t)((a_b0 + (tid >> 6))*NT + t)*512 + ccl*64 + (tid & 63)]);

        // ===== Phase A: scores(h) + A0 + softmax -> s'(t) in g_sw =====
        {
            u64 acc2[4] = {0ull, 0ull, 0ull, 0ull};
            {
                const double2* wp = (const double2*)g_Wscq + (a_ks*16)*NCM + (ccl*64 + a_ml);
                const float*  ak = sm + (bhalf*8 + a_bh*4)*C_BSTR + 512 + a_ks*64;
                #define AHALF(IT, WV) { \
                    u64 w01_ = __double_as_longlong((WV).x); \
                    u64 w23_ = __double_as_longlong((WV).y); \
                    const float* app_ = ak + (IT)*4; \
                    _Pragma("unroll") \
                    for (int j_ = 0; j_ < 4; ++j_) { \
                        u64 a01_ = *(const u64*)(app_ + j_*C_BSTR); \
                        u64 a23_ = *(const u64*)(app_ + j_*C_BSTR + 2); \
                        ffma2(acc2[j_], w01_, a01_); \
                        ffma2(acc2[j_], w23_, a23_); } }
                double2 V0 = wp[0], V1 = wp[NCM];
                #pragma unroll 1
                for (int it = 0; it < 16; it += 2) {
                    double2 N0 = wp[(it+2)*NCM];
                    AHALF(it, V0)
                    double2 N1 = wp[(it+3)*NCM];
                    AHALF(it+1, V1)
                    V0 = N0; V1 = N1;
                }
                #undef AHALF
            }
            {
                int base = A_PART + ((a_ks*64 + a_ml)*2 + a_bh)*5;
                #pragma unroll
                for (int jj = 0; jj < 4; ++jj) sm[base + jj] = pairsum(acc2[jj]);
            }
            __syncthreads();
            {
                int bl = tid >> 6, m = tid & 63;
                float s = a0r;
                #pragma unroll
                for (int ks = 0; ks < 4; ++ks)
                    s += sm[A_PART + ((ks*64 + m)*2 + (bl >> 2))*5 + (bl & 3)];
                sm[A_SCORE + bl*64 + m] = s;
            }
            __syncthreads();
            if (wid < 8) {
                float v0 = sm[A_SCORE + wid*64 + lane];
                float v1 = sm[A_SCORE + wid*64 + 32 + lane];
                float mx = fmaxf(v0, v1);
                #pragma unroll
                for (int o = 16; o; o >>= 1) mx = fmaxf(mx, __shfl_xor_sync(0xffffffffu, mx, o));
                float e0 = expf(v0 - mx), e1 = expf(v1 - mx);
                float s = e0 + e1;
                #pragma unroll
                for (int o = 16; o; o >>= 1) s += __shfl_xor_sync(0xffffffffu, s, o);
                float sc = gwreg / s;
                int b = a_b0 + wid;
                __stcg(&g_sw[b*NCM + ccl*64 + lane],      e0*sc);
                __stcg(&g_sw[b*NCM + ccl*64 + 32 + lane], e1*sc);
            }
        }
        group_sync(grp, gen);   // s'(t) complete group-wide

        // stage s'(t) into act rows [0:512)
        for (int idx = tid; idx < 16*128; idx += NTHR) {
            int bi = idx >> 7, k4 = idx & 127;
            int b = c_b0 + bi, k = k4*4;
            *(float4*)&sm[bi*C_BSTR + k] = __ldcg((const float4*)&g_sw[(b << 9) + k]);
        }
        __syncthreads();

        // ===== Phase C: 4-gate GEMM over K=768 [s',h], k-pair f32x2 =====
        {
            u64 acc2[16];
            #pragma unroll
            for (int i = 0; i < 16; ++i) acc2[i] = 0ull;
            {
                const int c_bq = (tid >> 4) & 3;
                const int k24 = c_ks * 24;
                const double2* w0 = (const double2*)g_W4q + ((0*192 + k24)*NH + hh);
                const double2* w1 = (const double2*)g_W4q + ((1*192 + k24)*NH + hh);
                const double2* w2 = (const double2*)g_W4q + ((2*192 + k24)*NH + hh);
                const double2* w3 = (const double2*)g_W4q + ((3*192 + k24)*NH + hh);
                const float*  ak = sm + (c_bq*4)*C_BSTR + c_ks*96;
                #define CHALF(IT, WA, WB2, WC, WD) { \
                    u64 wa01_ = __double_as_longlong((WA).x),  wa23_ = __double_as_longlong((WA).y); \
                    u64 wb01_ = __double_as_longlong((WB2).x), wb23_ = __double_as_longlong((WB2).y); \
                    u64 wc01_ = __double_as_longlong((WC).x),  wc23_ = __double_as_longlong((WC).y); \
                    u64 wd01_ = __double_as_longlong((WD).x),  wd23_ = __double_as_longlong((WD).y); \
                    const float* app_ = ak + (IT)*4; \
                    _Pragma("unroll") \
                    for (int j_ = 0; j_ < 4; ++j_) { \
                        u64 a01_ = *(const u64*)(app_ + j_*C_BSTR); \
                        u64 a23_ = *(const u64*)(app_ + j_*C_BSTR + 2); \
                        ffma2(acc2[0*4+j_], wa01_, a01_); ffma2(acc2[0*4+j_], wa23_, a23_); \
                        ffma2(acc2[1*4+j_], wb01_, a01_); ffma2(acc2[1*4+j_], wb23_, a23_); \
                        ffma2(acc2[2*4+j_], wc01_, a01_); ffma2(acc2[2*4+j_], wc23_, a23_); \
                        ffma2(acc2[3*4+j_], wd01_, a01_); ffma2(acc2[3*4+j_], wd23_, a23_); } }
                double2 Wa0 = w0[0],  Wb0 = w1[0],  Wc0 = w2[0],  Wd0 = w3[0];
                double2 Wa1 = w0[NH], Wb1 = w1[NH], Wc1 = w2[NH], Wd1 = w3[NH];
                #pragma unroll 1
                for (int it = 0; it < 24; it += 2) {
                    double2 Na = w0[(it+2)*NH], Nb = w1[(it+2)*NH],
                            Nc = w2[(it+2)*NH], Nd = w3[(it+2)*NH];
                    CHALF(it, Wa0, Wb0, Wc0, Wd0)
                    double2 Ma = w0[(it+3)*NH], Mb = w1[(it+3)*NH],
                            Mc = w2[(it+3)*NH], Md = w3[(it+3)*NH];
                    CHALF(it+1, Wa1, Wb1, Wc1, Wd1)
                    Wa0 = Na; Wb0 = Nb; Wc0 = Nc; Wd0 = Nd;
                    Wa1 = Ma; Wb1 = Mb; Wc1 = Mc; Wd1 = Md;
                }
                #undef CHALF
            }
            {   // partials to disjoint region
                const int c_bq = (tid >> 4) & 3;
                int base = C_PART + (c_ks*64 + c_bq*16 + c_hl)*17;
                #pragma unroll
                for (int v = 0; v < 16; ++v) sm[base + v] = pairsum(acc2[v]);
            }
            __syncthreads();
            if (tid < 256) {   // reduce 8 ks + G0, gates, register state
                int hl2 = tid & 15, bi = tid >> 4;
                int bq = bi >> 2, jx = bi & 3;
                int b = c_b0 + bi, h2 = sub*16 + hl2;
                float g0 = g0r0, g1 = g0r1, g2 = g0r2, g3 = g0r3;
                #pragma unroll
                for (int ks = 0; ks < 8; ++ks) {
                    const float* p = &sm[C_PART + (ks*64 + bq*16 + hl2)*17 + jx];
                    g0 += p[0]; g1 += p[4]; g2 += p[8]; g3 += p[12];
                }
                float ig = 1.f / (1.f + expf(-g0));
                float fg = 1.f / (1.f + expf(-g1));
                float og = 1.f / (1.f + expf(-g2));
                float cg = tanhf(g3);
                creg = fg * creg + ig * cg;
                float hn = og * tanhf(creg);
                __stcg(&g_hall[(((t+1)*NB + b) << 8) + h2], hn);
            }
        }
        group_sync(grp, gen);   // h(t+1) complete group-wide

        if (t + 1 < NT) {   // stage h(t+1) into act rows 512..768
            for (int idx = tid; idx < 16*64; idx += NTHR) {
                int bi = idx >> 6, k4 = idx & 63;
                *(float4*)&sm[bi*C_BSTR + 512 + k4*4] =
                    __ldcg((const float4*)&g_hall[(((t+1)*NB + c_b0 + bi) << 8) + k4*4]);
            }
            __syncthreads();
        }
    }
}

// ---------------- final: out[b,t,:] = h_{t+1} @ W_fc^T + b_fc ----------------
__global__ void out_gemm(const float* __restrict__ W_fc, const float* __restrict__ b_fc,
                         float* __restrict__ out)
{
    __shared__ float sa[16*256];
    int rt = blockIdx.x >> 2, dt = blockIdx.x & 3;
    int tid = threadIdx.x;           // 256
    int r0 = rt * 16;
    for (int idx = tid; idx < 16*64; idx += 256) {
        int row = idx >> 6, k4 = idx & 63;
        int r = r0 + row, b = r / NT, t = r % NT;
        *(float4*)&sa[row*256 + k4*4] =
            *(const float4*)&g_hall[(((t+1)*NB + b) << 8) + k4*4];
    }
    __syncthreads();
    int dl = tid & 63, rl = tid >> 6;
    int d = dt*64 + dl;
    float acc[4];
    #pragma unroll
    for (int i = 0; i < 4; ++i) acc[i] = 0.f;
    const float* wrow = W_fc + d*NH;
    #pragma unroll 4
    for (int k4 = 0; k4 < 64; ++k4) {
        float4 wv = *(const float4*)(wrow + k4*4);
        #pragma unroll
        for (int i = 0; i < 4; ++i) {
            float4 av = *(const float4*)&sa[(rl*4 + i)*256 + k4*4];
            FMA4(acc[i], wv, av);
        }
    }
    float bb = b_fc[d];
    #pragma unroll
    for (int i = 0; i < 4; ++i)
        out[(r0 + rl*4 + i)*ND + d] = acc[i] + bb;
}

// ---------------- launch ----------------
extern "C" void kernel_launch(void* const* d_in, const int* in_sizes, int n_in,
                              void* d_out, int out_size)
{
    const float* x        = (const float*)d_in[0];
    const float* xmean    = (const float*)d_in[1];
    const int*   clus     = (const int*)  d_in[2];
    const float* W_i      = (const float*)d_in[3];
    const float* b_i      = (const float*)d_in[4];
    const float* W_f      = (const float*)d_in[5];
    const float* b_f      = (const float*)d_in[6];
    const float* W_o      = (const float*)d_in[7];
    const float* b_o      = (const float*)d_in[8];
    const float* W_c      = (const float*)d_in[9];
    const float* b_c      = (const float*)d_in[10];
    const float* W_fc     = (const float*)d_in[11];
    const float* b_fc     = (const float*)d_in[12];
    const float* gz_w     = (const float*)d_in[13];
    const float* gz_b     = (const float*)d_in[14];
    const float* gzp_w    = (const float*)d_in[15];
    const float* gzp_b    = (const float*)d_in[16];
    const float* memory   = (const float*)d_in[17];
    const float* local_w  = (const float*)d_in[18];
    const float* global_w = (const float*)d_in[19];
    float* out = (float*)d_out;

    cudaFuncSetAttribute(rnn_kernel, cudaFuncAttributeMaxDynamicSharedMemorySize, SMEM_BYTES);

    prep1<<<512, 256>>>(x, xmean, clus, gz_w, gz_b, gzp_w, gzp_b, memory, local_w);
    prep2<<<32, 512>>>(W_fc, b_fc, local_w);
    prep3<<<128, 512>>>(W_i, W_f, W_o, W_c, b_i, b_f, b_o, b_c, W_fc, b_fc);
    prep4<<<900, 256>>>();
    pc_gemm<<<dim3(192, 24), 256>>>();
    rnn_kernel<<<GRID, NTHR, SMEM_BYTES>>>(global_w);
    out_gemm<<<3072, 256>>>(W_fc, b_fc, out);
}